// round 4
// baseline (speedup 1.0000x reference)
#include <cuda_runtime.h>

// Random_RNN two-hop sparse propagation — ONE fused persistent kernel.
//
// Hop1: acc1[j][b] = sum_{in-edges dst=j} w * x[b][src]
// Hop2: out[b][o]  = sum_{ass-edges dst=OUT0+o} w * acc1[src][b]
// Only ass-edges landing on OUTPUT nodes matter (~52K of ~891K) -> filter.
//
// Everything is latency-bound, and multi-launch graphs were eating ~50us in
// gaps/ramp. So: single launch, 296 co-resident CTAs (launch_bounds(512,2)
// guarantees 2 CTAs/SM residency), device-wide sense-reversing barriers
// between phases. Sense flips exactly twice per launch -> barrier state
// returns to initial -> graph replays are deterministic. Bucket counters are
// consumed-and-reset by the hop phases for the same reason.

#define B      128
#define IN_F   256
#define N_ASS  4096
#define OUT_F  256
#define ASS0   256
#define OUT0   (IN_F + N_ASS)   // 4352
#define CAP1   96               // assoc in-degree: E 12.8, sd 3.5  (>8 sigma headroom)
#define CAP2   448              // output in-degree: E 204.8, sd 14
#define NBLK   296
#define NTHR   512

__device__ float2       g_b1[N_ASS * CAP1];  // {src*B (int bits), w}
__device__ float2       g_b2[OUT_F * CAP2];
__device__ int          g_c1[N_ASS];         // zero at every launch entry
__device__ int          g_c2[OUT_F];
__device__ float        g_xT[IN_F * B];
__device__ float        g_acc1[N_ASS * B];
__device__ int          g_count;             // barrier arrivals (resets to 0 each barrier)
__device__ volatile int g_sense;             // flips per barrier; even #barriers/launch

__device__ __forceinline__ void grid_barrier(int* local_sense) {
    __syncthreads();
    if (threadIdx.x == 0) {
        int s = *local_sense ^ 1;
        __threadfence();                               // publish this block's writes
        if (atomicAdd(&g_count, 1) == NBLK - 1) {
            g_count = 0;
            __threadfence();
            g_sense = s;                               // release everyone
        } else {
            while (g_sense != s) {}                    // volatile spin
        }
        *local_sense = s;
    }
    __syncthreads();
    __threadfence();                                   // acquire other blocks' writes
}

__global__ void __launch_bounds__(NTHR, 2)
k_fused(const float* __restrict__ x,
        const int* __restrict__ in_src, const int* __restrict__ in_dst,
        const float* __restrict__ in_w, int E_in,
        const int* __restrict__ a_src, const int* __restrict__ a_dst,
        const float* __restrict__ a_w, int E_ass,
        float* __restrict__ out) {
    int tid = threadIdx.x;
    int i   = blockIdx.x * NTHR + tid;
    const int nt = NBLK * NTHR;                        // 151552
    int local_sense = 0;

    // ================= Phase A: transpose + bucket build =================
    // x [B][IN_F] -> xT [IN_F][B] (coalesced reads; scattered writes are tiny)
    for (int idx = i; idx < IN_F * B; idx += nt) {
        int b = idx >> 8, s = idx & 255;
        g_xT[s * B + b] = x[idx];
    }
    // hop1 edges (~52K): <1 edge/thread
    if (i < E_in) {
        int d   = in_dst[i] - ASS0;
        int pos = atomicAdd(&g_c1[d], 1);
        g_b1[d * CAP1 + pos] = make_float2(__int_as_float(in_src[i] * B), in_w[i]);
    }
    for (int e = i + nt; e < E_in; e += nt) {
        int d   = in_dst[e] - ASS0;
        int pos = atomicAdd(&g_c1[d], 1);
        g_b1[d * CAP1 + pos] = make_float2(__int_as_float(in_src[e] * B), in_w[e]);
    }
    // hop2 edges (~891K): int4 scan, 2 independent loads/iteration, filter hits
    {
        int E4 = E_ass >> 2;
        const int4* a4 = (const int4*)a_dst;
        for (int q = i; q < E4; q += 2 * nt) {
            int  q2 = q + nt;
            int4 dA = __ldg(&a4[q]);
            int4 dB = (q2 < E4) ? __ldg(&a4[q2]) : make_int4(0, 0, 0, 0);
#pragma unroll
            for (int h = 0; h < 2; h++) {
                int4 d4 = h ? dB : dA;
                int  e0 = (h ? q2 : q) << 2;
                if (h && q2 >= E4) break;
                int dd[4] = {d4.x, d4.y, d4.z, d4.w};
#pragma unroll
                for (int m = 0; m < 4; m++) {
                    if (dd[m] >= OUT0) {
                        int   d = dd[m] - OUT0;
                        int   s = __ldg(&a_src[e0 + m]) - ASS0;
                        float w = __ldg(&a_w[e0 + m]);
                        int pos = atomicAdd(&g_c2[d], 1);
                        g_b2[d * CAP2 + pos] = make_float2(__int_as_float(s * B), w);
                    }
                }
            }
        }
        for (int e = (E4 << 2) + i; e < E_ass; e += nt) {  // tail
            int d = a_dst[e];
            if (d >= OUT0) {
                int   dd = d - OUT0;
                int   s  = a_src[e] - ASS0;
                float w  = a_w[e];
                int pos  = atomicAdd(&g_c2[dd], 1);
                g_b2[dd * CAP2 + pos] = make_float2(__int_as_float(s * B), w);
            }
        }
    }

    grid_barrier(&local_sense);

    // ================= Phase B: hop1 gather =================
    // 4 nodes per block-iteration (128 threads each), 1024 groups over 296 blocks
    {
        __shared__ int sn[4];
        int g = tid >> 7, b = tid & 127;
        for (int it = blockIdx.x; it < N_ASS / 4; it += NBLK) {
            int j = (it << 2) + g;
            if (b == 0) { sn[g] = g_c1[j]; g_c1[j] = 0; }   // consume + reset
            __syncthreads();
            int n = sn[g];
            const float2* bk = &g_b1[j * CAP1];
            float r = 0.f;
            int e = 0;
            for (; e + 4 <= n; e += 4) {
                float2 p0 = bk[e], p1 = bk[e + 1], p2 = bk[e + 2], p3 = bk[e + 3];
                r += p0.y * g_xT[__float_as_int(p0.x) + b];
                r += p1.y * g_xT[__float_as_int(p1.x) + b];
                r += p2.y * g_xT[__float_as_int(p2.x) + b];
                r += p3.y * g_xT[__float_as_int(p3.x) + b];
            }
            for (; e < n; e++) { float2 p = bk[e]; r += p.y * g_xT[__float_as_int(p.x) + b]; }
            g_acc1[j * B + b] = r;
            __syncthreads();                                 // sn reused next iter
        }
    }

    grid_barrier(&local_sense);

    // ================= Phase C: hop2 gather =================
    // One output per block (first 256 blocks); 4 edge-groups x 128 batch threads,
    // smem-reduce the 4 partials. Cuts the dependent-load chain by 4x.
    if (blockIdx.x < OUT_F) {
        __shared__ int   sc;
        __shared__ float part[3][B];
        int o = blockIdx.x;
        int g = tid >> 7, b = tid & 127;
        if (tid == 0) { sc = g_c2[o]; g_c2[o] = 0; }         // consume + reset
        __syncthreads();
        int n  = sc;
        int e0 = (n * g)       >> 2;                         // contiguous chunk per group
        int e1 = (n * (g + 1)) >> 2;
        const float2* bk = &g_b2[o * CAP2];
        float r = 0.f;
        int e = e0;
        for (; e + 8 <= e1; e += 8) {
            float2 p[8];
#pragma unroll
            for (int k = 0; k < 8; k++) p[k] = bk[e + k];
#pragma unroll
            for (int k = 0; k < 8; k++) r += p[k].y * g_acc1[__float_as_int(p[k].x) + b];
        }
        for (; e < e1; e++) { float2 p = bk[e]; r += p.y * g_acc1[__float_as_int(p.x) + b]; }
        if (g > 0) part[g - 1][b] = r;
        __syncthreads();
        if (g == 0)
            out[b * OUT_F + o] = r + part[0][b] + part[1][b] + part[2][b];
    }
}

// ---------------------------------------------------------------- launch
extern "C" void kernel_launch(void* const* d_in, const int* in_sizes, int n_in,
                              void* d_out, int out_size) {
    const float* x      = (const float*)d_in[0];
    const float* in_w   = (const float*)d_in[1];
    const float* a_w    = (const float*)d_in[2];
    const int*   in_src = (const int*)d_in[3];
    const int*   in_dst = (const int*)d_in[4];
    const int*   a_src  = (const int*)d_in[5];
    const int*   a_dst  = (const int*)d_in[6];
    int E_in  = in_sizes[1];
    int E_ass = in_sizes[2];
    float* out = (float*)d_out;

    k_fused<<<NBLK, NTHR>>>(x, in_src, in_dst, in_w, E_in,
                            a_src, a_dst, a_w, E_ass, out);
}

// round 5
// speedup vs baseline: 1.2647x; 1.2647x over previous
#include <cuda_runtime.h>

// Random_RNN two-hop sparse propagation — max-parallelism 3-kernel pipeline.
//
// Hop1: acc1[j][b] = sum_{in-edges dst=j} w * x[b][src]
// Hop2: out[b][o]  = sum_{ass-edges dst=OUT0+o} w * acc1[src][b]
// Only ass-edges landing on OUTPUT nodes matter (~52K of ~891K) -> filter.
//
// Every phase is latency-bound (issue <6%, HBM <5% across 4 profiled rounds).
// Lever: bytes-in-flight = resident threads x independent loads per thread.
// So the build kernel uses ONE THREAD PER WORK ITEM (one int4 of the dst scan,
// one hop1 edge, one transpose element) -> the whole 3.5MB scan is in flight
// within ~one memory latency. Hop kernels use predicated/unrolled independent
// gathers. Counters are consumed-and-reset by the hop kernels so CUDA-graph
// replays see identical initial state.

#define B      128
#define IN_F   256
#define N_ASS  4096
#define OUT_F  256
#define ASS0   256
#define OUT0   (IN_F + N_ASS)   // 4352
#define CAP1   40               // assoc in-degree: E 12.8, sd 3.5 (max-of-4096 ~ 26)
#define CAP2   288              // output in-degree: E 204.8, sd 14 (max-of-256 ~ 252)
#define XT_N   (IN_F * B)       // 32768

__device__ float2 g_b1[N_ASS * CAP1];   // {src*B (int bits), w}  1.3 MB
__device__ float2 g_b2[OUT_F * CAP2];   //                        0.6 MB
__device__ int    g_c1[N_ASS];          // zero at every launch entry
__device__ int    g_c2[OUT_F];
__device__ float  g_xT[IN_F * B];       // x transposed [src][b]
__device__ float  g_acc1[N_ASS * B];    // assoc activations (2 MB)

// ---------------------------------------------------------------- build
// One thread per work item; flat index space:
//   [0, XT_N)               transpose element
//   [XT_N, XT_N+E_in)       hop1 edge
//   [.., .. + E4)           one int4 of a_dst  (4 edges)
//   [.., .. + tail)         leftover a_dst edges
__global__ void __launch_bounds__(256)
k_build(const float* __restrict__ x,
        const int* __restrict__ in_src, const int* __restrict__ in_dst,
        const float* __restrict__ in_w, int E_in,
        const int* __restrict__ a_src, const int* __restrict__ a_dst,
        const float* __restrict__ a_w, int E_ass) {
    int i = blockIdx.x * 256 + threadIdx.x;

    if (i < XT_N) {                                    // transpose
        int b = i >> 8, s = i & 255;                   // IN_F == 256
        g_xT[s * B + b] = x[i];
        return;
    }
    int j = i - XT_N;
    if (j < E_in) {                                    // hop1 edge
        int d   = in_dst[j] - ASS0;
        int s   = in_src[j];
        float w = in_w[j];
        int pos = atomicAdd(&g_c1[d], 1);
        g_b1[d * CAP1 + pos] = make_float2(__int_as_float(s * B), w);
        return;
    }
    int q  = j - E_in;
    int E4 = E_ass >> 2;
    if (q < E4) {                                      // 4 hop2 dst checks
        int4 d4 = __ldg(&((const int4*)a_dst)[q]);
        int  e0 = q << 2;
        int dd[4] = {d4.x, d4.y, d4.z, d4.w};
#pragma unroll
        for (int m = 0; m < 4; m++) {
            if (dd[m] >= OUT0) {
                int   d = dd[m] - OUT0;
                int   s = __ldg(&a_src[e0 + m]) - ASS0;
                float w = __ldg(&a_w[e0 + m]);
                int pos = atomicAdd(&g_c2[d], 1);
                g_b2[d * CAP2 + pos] = make_float2(__int_as_float(s * B), w);
            }
        }
        return;
    }
    int t = q - E4;                                    // tail edges (E_ass % 4)
    int e = (E4 << 2) + t;
    if (e < E_ass) {
        int d = a_dst[e];
        if (d >= OUT0) {
            int   dd = d - OUT0;
            int   s  = a_src[e] - ASS0;
            float w  = a_w[e];
            int pos  = atomicAdd(&g_c2[dd], 1);
            g_b2[dd * CAP2 + pos] = make_float2(__int_as_float(s * B), w);
        }
    }
}

// ---------------------------------------------------------------- hop 1
// One 128-thread block per assoc node. ~13 edges: predicated 4-wide rounds so
// all 4 loads of a round are independent (no dynamic-loop serialization).
__global__ void __launch_bounds__(128) k_hop1() {
    int j = blockIdx.x, b = threadIdx.x;
    __shared__ int sn;
    if (b == 0) { sn = g_c1[j]; g_c1[j] = 0; }         // consume + reset
    __syncthreads();
    int n = sn;
    const float2* bk = &g_b1[j * CAP1];
    float r = 0.f;
    for (int e = 0; e < n; e += 4) {
        float2 p0 = bk[e];
        float2 p1 = (e + 1 < n) ? bk[e + 1] : make_float2(0.f, 0.f);
        float2 p2 = (e + 2 < n) ? bk[e + 2] : make_float2(0.f, 0.f);
        float2 p3 = (e + 3 < n) ? bk[e + 3] : make_float2(0.f, 0.f);
        r += p0.y * g_xT[__float_as_int(p0.x) + b];
        if (e + 1 < n) r += p1.y * g_xT[__float_as_int(p1.x) + b];
        if (e + 2 < n) r += p2.y * g_xT[__float_as_int(p2.x) + b];
        if (e + 3 < n) r += p3.y * g_xT[__float_as_int(p3.x) + b];
    }
    g_acc1[j * B + b] = r;                             // coalesced
}

// ---------------------------------------------------------------- hop 2
// One output per block; 4 edge-groups x 128 batch threads; 8-wide unroll
// inside each group (~51 edges -> ~7 independent-load rounds); smem reduce.
__global__ void __launch_bounds__(512) k_hop2(float* __restrict__ out) {
    __shared__ int   sc;
    __shared__ float part[3][B];
    int o = blockIdx.x;
    int g = threadIdx.x >> 7, b = threadIdx.x & 127;
    if (threadIdx.x == 0) { sc = g_c2[o]; g_c2[o] = 0; }   // consume + reset
    __syncthreads();
    int n  = sc;
    int e0 = (n * g)       >> 2;
    int e1 = (n * (g + 1)) >> 2;
    const float2* bk = &g_b2[o * CAP2];
    float r = 0.f;
    int e = e0;
    for (; e + 8 <= e1; e += 8) {
        float2 p[8];
#pragma unroll
        for (int k = 0; k < 8; k++) p[k] = bk[e + k];
#pragma unroll
        for (int k = 0; k < 8; k++) r += p[k].y * g_acc1[__float_as_int(p[k].x) + b];
    }
    for (; e < e1; e++) { float2 p = bk[e]; r += p.y * g_acc1[__float_as_int(p.x) + b]; }
    if (g > 0) part[g - 1][b] = r;
    __syncthreads();
    if (g == 0)
        out[b * OUT_F + o] = r + part[0][b] + part[1][b] + part[2][b];
}

// ---------------------------------------------------------------- launch
extern "C" void kernel_launch(void* const* d_in, const int* in_sizes, int n_in,
                              void* d_out, int out_size) {
    const float* x      = (const float*)d_in[0];
    const float* in_w   = (const float*)d_in[1];
    const float* a_w    = (const float*)d_in[2];
    const int*   in_src = (const int*)d_in[3];
    const int*   in_dst = (const int*)d_in[4];
    const int*   a_src  = (const int*)d_in[5];
    const int*   a_dst  = (const int*)d_in[6];
    int E_in  = in_sizes[1];
    int E_ass = in_sizes[2];
    float* out = (float*)d_out;

    int E4    = E_ass >> 2;
    int tail  = E_ass - (E4 << 2);
    int items = XT_N + E_in + E4 + tail;               // one thread each
    int blk   = (items + 255) >> 8;

    k_build<<<blk, 256>>>(x, in_src, in_dst, in_w, E_in, a_src, a_dst, a_w, E_ass);
    k_hop1 <<<N_ASS, 128>>>();
    k_hop2 <<<OUT_F, 512>>>(out);
}

// round 7
// speedup vs baseline: 1.3438x; 1.0625x over previous
#include <cuda_runtime.h>

// Random_RNN two-hop sparse propagation — 3-kernel bucket pipeline, short chains.
// (Resubmit of R6 design: R6 bench died at harness device-init with "device busy"
//  — infra transient, no kernel signal.)
//
// Hop1: acc1[j][b] = sum_{in-edges dst=j} w * x[b][src]
// Hop2: out[b][o]  = sum_{ass-edges dst=OUT0+o} w * acc1[src][b]
// Only ass-edges landing on OUTPUT nodes matter (~52K of ~891K) -> filter.
//
// (src,dst) pairs are unique per hop, so bucket insertion order only permutes
// the fp sum (rel_err ~3e-7 observed). Counters are consumed-and-reset by the
// hop kernels so every launch/replay sees identical initial state.
//
// Evidence: all shapes sit at issue<6%, HBM<5% — latency-floor bound. So:
// minimum phases (3 launches), one int4 scan of a_dst, 8-wide predicated
// gather rounds (hop1 ~2 rounds/node, hop2 ~7 rounds via 4-way edge split).

#define B      128
#define IN_F   256
#define N_ASS  4096
#define OUT_F  256
#define ASS0   256
#define OUT0   (IN_F + N_ASS)   // 4352
#define CAP1   40               // assoc in-degree: E 12.8, sd 3.5 (max ~26)
#define CAP2   288              // output in-degree: E 204.8, sd 14 (max ~252)
#define XT_N   (IN_F * B)       // 32768

__device__ float2 g_b1[N_ASS * CAP1];   // {src*B (int bits), w}  1.3 MB
__device__ float2 g_b2[OUT_F * CAP2];   //                        0.6 MB
__device__ int    g_c1[N_ASS];          // zero at every launch entry
__device__ int    g_c2[OUT_F];
__device__ float  g_xT[IN_F * B];       // x transposed [src][b]
__device__ float  g_acc1[N_ASS * B];    // assoc activations (2 MB, L2-resident)

// ---------------------------------------------------------------- build
// Grid-stride, 1184 blocks x 256; 22 regs -> 8 CTAs/SM resident (one wave).
__global__ void __launch_bounds__(256, 8)
k_build(const float* __restrict__ x,
        const int* __restrict__ in_src, const int* __restrict__ in_dst,
        const float* __restrict__ in_w, int E_in,
        const int* __restrict__ a_src, const int* __restrict__ a_dst,
        const float* __restrict__ a_w, int E_ass) {
    const int i  = blockIdx.x * 256 + threadIdx.x;
    const int nt = gridDim.x * 256;

    // x [B][IN_F] -> xT [IN_F][B]
    for (int idx = i; idx < XT_N; idx += nt) {
        int b = idx >> 8, s = idx & 255;               // IN_F == 256
        g_xT[s * B + b] = x[idx];
    }

    // hop1 edges (~52K)
    for (int e = i; e < E_in; e += nt) {
        int   d = in_dst[e] - ASS0;
        int   s = in_src[e];
        float w = in_w[e];
        int pos = atomicAdd(&g_c1[d], 1);
        g_b1[d * CAP1 + pos] = make_float2(__int_as_float(s * B), w);
    }

    // hop2 edges (~891K): int4 dst scan, filter dst >= OUT0 (~5.9% hit)
    const int  E4 = E_ass >> 2;
    const int4* a4 = (const int4*)a_dst;
    for (int q = i; q < E4; q += nt) {
        int4 d4 = __ldg(&a4[q]);
        int  e0 = q << 2;
        int dd[4] = {d4.x, d4.y, d4.z, d4.w};
#pragma unroll
        for (int m = 0; m < 4; m++) {
            if (dd[m] >= OUT0) {
                int   d = dd[m] - OUT0;
                int   s = __ldg(&a_src[e0 + m]) - ASS0;  // hoisted before atomic
                float w = __ldg(&a_w[e0 + m]);
                int pos = atomicAdd(&g_c2[d], 1);
                g_b2[d * CAP2 + pos] = make_float2(__int_as_float(s * B), w);
            }
        }
    }
    for (int e = (E4 << 2) + i; e < E_ass; e += nt) {  // tail (E_ass % 4)
        int d = a_dst[e];
        if (d >= OUT0) {
            int   dd = d - OUT0;
            int   s  = a_src[e] - ASS0;
            float w  = a_w[e];
            int pos  = atomicAdd(&g_c2[dd], 1);
            g_b2[dd * CAP2 + pos] = make_float2(__int_as_float(s * B), w);
        }
    }
}

// ---------------------------------------------------------------- hop 1
// 2 nodes per 256-thread block; 8-wide predicated rounds (~2 rounds/node).
// Guarded loads: entries beyond n are stale from a prior replay — never read.
__global__ void __launch_bounds__(256) k_hop1() {
    __shared__ int sn[2];
    int g = threadIdx.x >> 7;              // 0..1
    int b = threadIdx.x & 127;
    int j = (blockIdx.x << 1) + g;
    if (b == 0) { sn[g] = g_c1[j]; g_c1[j] = 0; }      // consume + reset
    __syncthreads();
    int n = sn[g];
    const float2* bk = &g_b1[j * CAP1];
    float r = 0.f;
    for (int e = 0; e < n; e += 8) {
        float2 p[8];
#pragma unroll
        for (int k = 0; k < 8; k++)
            p[k] = (e + k < n) ? __ldg(&bk[e + k]) : make_float2(0.f, 0.f);
#pragma unroll
        for (int k = 0; k < 8; k++)
            r += p[k].y * g_xT[__float_as_int(p[k].x) + b];   // idx 0 when padded
    }
    g_acc1[j * B + b] = r;                             // coalesced
}

// ---------------------------------------------------------------- hop 2
// One output per block; 4 edge-groups x 128 batch threads (~51 edges each),
// 8-wide predicated rounds (~7 rounds), smem reduce of the 4 partials.
__global__ void __launch_bounds__(512) k_hop2(float* __restrict__ out) {
    __shared__ int   sc;
    __shared__ float part[3][B];
    int o = blockIdx.x;
    int g = threadIdx.x >> 7, b = threadIdx.x & 127;
    if (threadIdx.x == 0) { sc = g_c2[o]; g_c2[o] = 0; }   // consume + reset
    __syncthreads();
    int n  = sc;
    int e0 = (n * g)       >> 2;
    int e1 = (n * (g + 1)) >> 2;
    const float2* bk = &g_b2[o * CAP2];
    float r = 0.f;
    for (int e = e0; e < e1; e += 8) {
        float2 p[8];
#pragma unroll
        for (int k = 0; k < 8; k++)
            p[k] = (e + k < e1) ? __ldg(&bk[e + k]) : make_float2(0.f, 0.f);
#pragma unroll
        for (int k = 0; k < 8; k++)
            r += p[k].y * g_acc1[__float_as_int(p[k].x) + b];
    }
    if (g > 0) part[g - 1][b] = r;
    __syncthreads();
    if (g == 0)
        out[b * OUT_F + o] = r + part[0][b] + part[1][b] + part[2][b];
}

// ---------------------------------------------------------------- launch
extern "C" void kernel_launch(void* const* d_in, const int* in_sizes, int n_in,
                              void* d_out, int out_size) {
    const float* x      = (const float*)d_in[0];
    const float* in_w   = (const float*)d_in[1];
    const float* a_w    = (const float*)d_in[2];
    const int*   in_src = (const int*)d_in[3];
    const int*   in_dst = (const int*)d_in[4];
    const int*   a_src  = (const int*)d_in[5];
    const int*   a_dst  = (const int*)d_in[6];
    int E_in  = in_sizes[1];
    int E_ass = in_sizes[2];
    float* out = (float*)d_out;

    k_build<<<1184, 256>>>(x, in_src, in_dst, in_w, E_in,
                           a_src, a_dst, a_w, E_ass);
    k_hop1 <<<N_ASS / 2, 256>>>();
    k_hop2 <<<OUT_F, 512>>>(out);
}

// round 8
// speedup vs baseline: 3.4486x; 2.5664x over previous
#include <cuda_runtime.h>

// Random_RNN two-hop sparse propagation — 3-kernel bucket pipeline.
// KEY FIX this round: bucket counters padded to ONE PER 128B CACHE LINE.
// L2 atomic units serialize per line; 52K increments on 256 contiguous ints
// (8 lines) was ~20K serialized cycles = the entire 22us build time seen in
// EVERY previous round. Stride-32 padding spreads them across 256/4096 lines.
//
// Hop1: acc1[j][b] = sum_{in-edges dst=j} w * x[b][src]
// Hop2: out[b][o]  = sum_{ass-edges dst=OUT0+o} w * acc1[src][b]
// Only ass-edges landing on OUTPUT nodes matter (~52K of ~891K) -> filter.
// Counters are consumed-and-reset by the hop kernels so every launch/replay
// sees identical initial state.

#define B      128
#define IN_F   256
#define N_ASS  4096
#define OUT_F  256
#define ASS0   256
#define OUT0   (IN_F + N_ASS)   // 4352
#define CAP1   40               // assoc in-degree: E 12.8, sd 3.5 (max ~26)
#define CAP2   288              // output in-degree: E 204.8, sd 14 (max ~252)
#define XT_N   (IN_F * B)       // 32768
#define CSTR   32               // counter stride: 32 ints = 128B = 1 L2 line

__device__ float2 g_b1[N_ASS * CAP1];   // {src*B (int bits), w}  1.3 MB
__device__ float2 g_b2[OUT_F * CAP2];   //                        0.6 MB
__device__ int    g_c1[N_ASS * CSTR];   // one counter per line (512 KB)
__device__ int    g_c2[OUT_F * CSTR];   // one counter per line (32 KB)
__device__ float  g_xT[IN_F * B];       // x transposed [src][b]
__device__ float  g_acc1[N_ASS * B];    // assoc activations (2 MB, L2-resident)

// ---------------------------------------------------------------- build
__global__ void __launch_bounds__(256, 8)
k_build(const float* __restrict__ x,
        const int* __restrict__ in_src, const int* __restrict__ in_dst,
        const float* __restrict__ in_w, int E_in,
        const int* __restrict__ a_src, const int* __restrict__ a_dst,
        const float* __restrict__ a_w, int E_ass) {
    const int i  = blockIdx.x * 256 + threadIdx.x;
    const int nt = gridDim.x * 256;

    // x [B][IN_F] -> xT [IN_F][B]
    for (int idx = i; idx < XT_N; idx += nt) {
        int b = idx >> 8, s = idx & 255;               // IN_F == 256
        g_xT[s * B + b] = x[idx];
    }

    // hop1 edges (~52K)
    for (int e = i; e < E_in; e += nt) {
        int   d = in_dst[e] - ASS0;
        int   s = in_src[e];
        float w = in_w[e];
        int pos = atomicAdd(&g_c1[d * CSTR], 1);       // line-private counter
        g_b1[d * CAP1 + pos] = make_float2(__int_as_float(s * B), w);
    }

    // hop2 edges (~891K): int4 dst scan, filter dst >= OUT0 (~5.9% hit)
    const int  E4 = E_ass >> 2;
    const int4* a4 = (const int4*)a_dst;
    for (int q = i; q < E4; q += nt) {
        int4 d4 = __ldg(&a4[q]);
        int  e0 = q << 2;
        int dd[4] = {d4.x, d4.y, d4.z, d4.w};
#pragma unroll
        for (int m = 0; m < 4; m++) {
            if (dd[m] >= OUT0) {
                int   d = dd[m] - OUT0;
                int   s = __ldg(&a_src[e0 + m]) - ASS0;  // hoisted before atomic
                float w = __ldg(&a_w[e0 + m]);
                int pos = atomicAdd(&g_c2[d * CSTR], 1); // line-private counter
                g_b2[d * CAP2 + pos] = make_float2(__int_as_float(s * B), w);
            }
        }
    }
    for (int e = (E4 << 2) + i; e < E_ass; e += nt) {  // tail (E_ass % 4)
        int d = a_dst[e];
        if (d >= OUT0) {
            int   dd = d - OUT0;
            int   s  = a_src[e] - ASS0;
            float w  = a_w[e];
            int pos  = atomicAdd(&g_c2[dd * CSTR], 1);
            g_b2[dd * CAP2 + pos] = make_float2(__int_as_float(s * B), w);
        }
    }
}

// ---------------------------------------------------------------- hop 1
// 2 nodes per 256-thread block; 8-wide predicated rounds (~2 rounds/node).
// Guarded loads: entries beyond n are stale from a prior replay — never read.
__global__ void __launch_bounds__(256) k_hop1() {
    __shared__ int sn[2];
    int g = threadIdx.x >> 7;              // 0..1
    int b = threadIdx.x & 127;
    int j = (blockIdx.x << 1) + g;
    if (b == 0) { sn[g] = g_c1[j * CSTR]; g_c1[j * CSTR] = 0; }  // consume+reset
    __syncthreads();
    int n = sn[g];
    const float2* bk = &g_b1[j * CAP1];
    float r = 0.f;
    for (int e = 0; e < n; e += 8) {
        float2 p[8];
#pragma unroll
        for (int k = 0; k < 8; k++)
            p[k] = (e + k < n) ? __ldg(&bk[e + k]) : make_float2(0.f, 0.f);
#pragma unroll
        for (int k = 0; k < 8; k++)
            r += p[k].y * g_xT[__float_as_int(p[k].x) + b];   // idx 0 when padded
    }
    g_acc1[j * B + b] = r;                             // coalesced
}

// ---------------------------------------------------------------- hop 2
// One output per block; 4 edge-groups x 128 batch threads (~51 edges each),
// 8-wide predicated rounds (~7 rounds), smem reduce of the 4 partials.
__global__ void __launch_bounds__(512) k_hop2(float* __restrict__ out) {
    __shared__ int   sc;
    __shared__ float part[3][B];
    int o = blockIdx.x;
    int g = threadIdx.x >> 7, b = threadIdx.x & 127;
    if (threadIdx.x == 0) { sc = g_c2[o * CSTR]; g_c2[o * CSTR] = 0; }
    __syncthreads();
    int n  = sc;
    int e0 = (n * g)       >> 2;
    int e1 = (n * (g + 1)) >> 2;
    const float2* bk = &g_b2[o * CAP2];
    float r = 0.f;
    for (int e = e0; e < e1; e += 8) {
        float2 p[8];
#pragma unroll
        for (int k = 0; k < 8; k++)
            p[k] = (e + k < e1) ? __ldg(&bk[e + k]) : make_float2(0.f, 0.f);
#pragma unroll
        for (int k = 0; k < 8; k++)
            r += p[k].y * g_acc1[__float_as_int(p[k].x) + b];
    }
    if (g > 0) part[g - 1][b] = r;
    __syncthreads();
    if (g == 0)
        out[b * OUT_F + o] = r + part[0][b] + part[1][b] + part[2][b];
}

// ---------------------------------------------------------------- launch
extern "C" void kernel_launch(void* const* d_in, const int* in_sizes, int n_in,
                              void* d_out, int out_size) {
    const float* x      = (const float*)d_in[0];
    const float* in_w   = (const float*)d_in[1];
    const float* a_w    = (const float*)d_in[2];
    const int*   in_src = (const int*)d_in[3];
    const int*   in_dst = (const int*)d_in[4];
    const int*   a_src  = (const int*)d_in[5];
    const int*   a_dst  = (const int*)d_in[6];
    int E_in  = in_sizes[1];
    int E_ass = in_sizes[2];
    float* out = (float*)d_out;

    k_build<<<1184, 256>>>(x, in_src, in_dst, in_w, E_in,
                           a_src, a_dst, a_w, E_ass);
    k_hop1 <<<N_ASS / 2, 256>>>();
    k_hop2 <<<OUT_F, 512>>>(out);
}